// round 4
// baseline (speedup 1.0000x reference)
#include <cuda_runtime.h>
#include <cstdint>

// SigCubicalEcc round 4.
// Per-pixel sigmoids + max-decomposition (sigma monotone => sigma(min f) = max sigma),
// with the cross-lane horizontal-edge term folded into the E domain:
//   max(s1, s_next) = sigma(min(e1, e_next)),  min(e1,e_next) step-invariant.
// E = 2^(K*x) precomputed globally into a padded [img][65][66] buffer:
//   row 0 = +inf (top halo), cols 64..65 = +inf (right halo).
// Main kernel: rows outer, 4 steps inner; no smem, no shfl, no syncthreads.

#define HH 64
#define WW 64
#define STEPS 32
#define GROUPS 8
#define SPG (STEPS / GROUPS)    // 4 steps per block
#define THREADS 128
#define NWARP 4
#define ROWS_PER_WARP 16
#define EPITCH 66
#define EROWS 65                // row 0 is +inf pad
#define NIMG 192
#define EIMG (EROWS * EPITCH)   // 4290

__device__ float Ebuf[NIMG * EIMG];   // 3.3 MB scratch (fits L2)

__device__ __forceinline__ float ex2_approx(float x) {
    float y;
    asm("ex2.approx.ftz.f32 %0, %1;" : "=f"(y) : "f"(x));
    return y;
}
__device__ __forceinline__ float rcp_approx(float x) {
    float y;
    asm("rcp.approx.ftz.f32 %0, %1;" : "=f"(y) : "f"(x));
    return y;
}

// Fused: build padded E buffer and zero the output.
__global__ void prep_kernel(const float* __restrict__ x, float* __restrict__ out,
                            int out_n) {
    const float K = 200.0f * 1.4426950408889634f;
    int idx = blockIdx.x * blockDim.x + threadIdx.x;
    if (idx < out_n) out[idx] = 0.0f;
    if (idx >= NIMG * EIMG) return;
    int img = idx / EIMG;
    int rem = idx - img * EIMG;
    int row = rem / EPITCH;
    int col = rem - row * EPITCH;
    float v;
    if (row == 0 || col >= WW) {
        v = __int_as_float(0x7f800000);   // +inf
    } else {
        float xv = x[img * (HH * WW) + (row - 1) * WW + col];
        v = ex2_approx(xv * K);           // overflow to +inf is the correct limit
    }
    Ebuf[idx] = v;
}

__global__ __launch_bounds__(THREADS)
void sig_cubical_ecc_kernel(float* __restrict__ out) {
    const int img   = blockIdx.x >> 3;          // / GROUPS
    const int group = blockIdx.x & (GROUPS - 1);
    const int tid   = threadIdx.x;
    const int lane  = tid & 31;
    const int warp  = tid >> 5;

    const float K = 200.0f * 1.4426950408889634f;

    // c_j = 2^(-K * t_j) for the 4 steps this block owns
    float cj[SPG];
#pragma unroll
    for (int jj = 0; jj < SPG; jj++) {
        int j = group * SPG + jj;
        float tj = 0.02f + (float)j * (0.26f / 31.0f);
        cj[jj] = ex2_approx(-K * tj);
    }

    const float* Ei = Ebuf + img * EIMG;
    const int p0 = warp * ROWS_PER_WARP;        // padded halo row index

    // ---- halo row: per-step prev state ----
    float sp0[SPG], sp1[SPG], mp0[SPG], mp1[SPG], acc[SPG];
    {
        const float* rp = Ei + p0 * EPITCH + 2 * lane;
        float2 e = *reinterpret_cast<const float2*>(rp);
        float em = fminf(e.y, rp[2]);
#pragma unroll
        for (int jj = 0; jj < SPG; jj++) {
            sp0[jj] = rcp_approx(fmaf(e.x, cj[jj], 1.0f));
            sp1[jj] = rcp_approx(fmaf(e.y, cj[jj], 1.0f));
            mp1[jj] = rcp_approx(fmaf(em,  cj[jj], 1.0f));
            mp0[jj] = fmaxf(sp0[jj], sp1[jj]);
            acc[jj] = 0.0f;
        }
    }

    // ---- 16 data rows ----
#pragma unroll 2
    for (int i = 1; i <= ROWS_PER_WARP; i++) {
        const float* rp = Ei + (p0 + i) * EPITCH + 2 * lane;
        float2 e = *reinterpret_cast<const float2*>(rp);
        float e2 = rp[2];
        float em = fminf(e.y, e2);
#pragma unroll
        for (int jj = 0; jj < SPG; jj++) {
            float s0 = rcp_approx(fmaf(e.x, cj[jj], 1.0f));
            float s1 = rcp_approx(fmaf(e.y, cj[jj], 1.0f));
            float m1 = rcp_approx(fmaf(em,  cj[jj], 1.0f));
            float m0 = fmaxf(s0, s1);

            float eh    = fmaxf(s0, sp0[jj]);
            float ehsel = (lane == 0) ? s0 : eh;  // left-boundary cancellation
            acc[jj] += (fminf(s0, s1) - m1)
                     + (fmaxf(m0, mp0[jj]) - ehsel)
                     + (fmaxf(m1, mp1[jj]) - fmaxf(s1, sp1[jj]));

            sp0[jj] = s0; sp1[jj] = s1; mp0[jj] = m0; mp1[jj] = m1;
        }
    }

    // ---- bottom boundary (vertex row 64): s-row is all zeros ----
    if (warp == NWARP - 1) {
#pragma unroll
        for (int jj = 0; jj < SPG; jj++) {
            float ehsel = (lane == 0) ? 0.0f : sp0[jj];
            acc[jj] += (mp0[jj] - ehsel) + (mp1[jj] - sp1[jj]);
        }
    }

    // ---- warp reduce + atomic ----
#pragma unroll
    for (int jj = 0; jj < SPG; jj++) {
        float v = acc[jj];
#pragma unroll
        for (int o = 16; o > 0; o >>= 1)
            v += __shfl_xor_sync(0xffffffffu, v, o);
        if (lane == 0)
            atomicAdd(&out[img * STEPS + group * SPG + jj], v);
    }
}

extern "C" void kernel_launch(void* const* d_in, const int* in_sizes, int n_in,
                              void* d_out, int out_size) {
    const float* x = (const float*)d_in[0];
    float* out = (float*)d_out;

    int prep_n = NIMG * EIMG;
    prep_kernel<<<(prep_n + 255) / 256, 256>>>(x, out, out_size);
    sig_cubical_ecc_kernel<<<NIMG * GROUPS, THREADS>>>(out);
}

// round 5
// speedup vs baseline: 1.1081x; 1.1081x over previous
#include <cuda_runtime.h>
#include <cstdint>

// SigCubicalEcc round 5 = round 3 formula (2 RCP + 1 SHFL per warp-row-step)
//   + step-batching (4 steps per row-load)
//   + globally precomputed E = 2^(K*x) (one EX2 per pixel total),
//     staged into smem per block via float4 copies.
//
// ECC_j = Sum_v max(m, m_up) - Sum_eh max(s, s_up) - Sum_ev m + Sum_f s
// with s = sigma per pixel, m = horizontal-pair max, sigma monotone.

#define HH 64
#define WW 64
#define STEPS 32
#define GROUPS 8
#define SPG (STEPS / GROUPS)    // 4 steps per block
#define THREADS 128
#define NWARP 4
#define ROWS_PER_WARP 16
#define EROWS 65                // row 0 = +inf halo
#define NIMG 192
#define EIMG (EROWS * WW)       // 4160 floats per image

__device__ float Ebuf[NIMG * EIMG];   // 3.2 MB scratch (L2-resident)

__device__ __forceinline__ float ex2_approx(float x) {
    float y;
    asm("ex2.approx.ftz.f32 %0, %1;" : "=f"(y) : "f"(x));
    return y;
}
__device__ __forceinline__ float rcp_approx(float x) {
    float y;
    asm("rcp.approx.ftz.f32 %0, %1;" : "=f"(y) : "f"(x));
    return y;
}

// Fused: build padded E buffer and zero the output.
__global__ void prep_kernel(const float* __restrict__ x, float* __restrict__ out,
                            int out_n) {
    const float K = 200.0f * 1.4426950408889634f;
    int idx = blockIdx.x * blockDim.x + threadIdx.x;
    if (idx < out_n) out[idx] = 0.0f;
    if (idx >= NIMG * EIMG) return;
    int img = idx / EIMG;
    int rem = idx - img * EIMG;
    int row = rem >> 6;          // /64
    int col = rem & 63;
    float v;
    if (row == 0) {
        v = __int_as_float(0x7f800000);   // +inf => sigma = 0
    } else {
        float xv = x[img * (HH * WW) + (row - 1) * WW + col];
        v = ex2_approx(xv * K);           // overflow to +inf is the correct limit
    }
    Ebuf[idx] = v;
}

__global__ __launch_bounds__(THREADS)
void sig_cubical_ecc_kernel(float* __restrict__ out) {
    __shared__ float Es[EIMG];   // 16.6 KB

    const int img   = blockIdx.x >> 3;          // / GROUPS
    const int group = blockIdx.x & (GROUPS - 1);
    const int tid   = threadIdx.x;
    const int lane  = tid & 31;
    const int warp  = tid >> 5;

    const float K = 200.0f * 1.4426950408889634f;

    // ---- stage E image into smem (float4) ----
    {
        const float4* src = reinterpret_cast<const float4*>(Ebuf + img * EIMG);
        float4* dst = reinterpret_cast<float4*>(Es);
        for (int i = tid; i < EIMG / 4; i += THREADS) dst[i] = src[i];
    }
    __syncthreads();

    // c_j = 2^(-K * t_j) for the 4 steps this block owns
    float cj[SPG];
#pragma unroll
    for (int jj = 0; jj < SPG; jj++) {
        int j = group * SPG + jj;
        float tj = 0.02f + (float)j * (0.26f / 31.0f);
        cj[jj] = ex2_approx(-K * tj);
    }

    const int p0 = warp * ROWS_PER_WARP;        // halo row in padded smem coords
    const float* base = Es + 2 * lane;

    // ---- halo row (smem row p0): per-step prev state ----
    float sp0[SPG], sp1[SPG], mp0[SPG], mp1[SPG], acc[SPG];
    {
        float2 e = *reinterpret_cast<const float2*>(base + p0 * WW);
#pragma unroll
        for (int jj = 0; jj < SPG; jj++) {
            float s0 = rcp_approx(fmaf(e.x, cj[jj], 1.0f));
            float s1 = rcp_approx(fmaf(e.y, cj[jj], 1.0f));
            float sn = __shfl_down_sync(0xffffffffu, s0, 1);
            sn = (lane == 31) ? 0.0f : sn;
            sp0[jj] = s0; sp1[jj] = s1;
            mp0[jj] = fmaxf(s0, s1);
            mp1[jj] = fmaxf(s1, sn);
            acc[jj] = 0.0f;
        }
    }

    // ---- 16 data rows ----
#pragma unroll 4
    for (int i = 1; i <= ROWS_PER_WARP; i++) {
        float2 e = *reinterpret_cast<const float2*>(base + (p0 + i) * WW);
#pragma unroll
        for (int jj = 0; jj < SPG; jj++) {
            float s0 = rcp_approx(fmaf(e.x, cj[jj], 1.0f));
            float s1 = rcp_approx(fmaf(e.y, cj[jj], 1.0f));
            float sn = __shfl_down_sync(0xffffffffu, s0, 1);
            sn = (lane == 31) ? 0.0f : sn;
            float m0 = fmaxf(s0, s1);
            float m1 = fmaxf(s1, sn);

            float eh    = fmaxf(s0, sp0[jj]);
            float ehsel = (lane == 0) ? s0 : eh;   // left-boundary cancellation
            acc[jj] += (fminf(s0, s1) - m1)
                     + (fmaxf(m0, mp0[jj]) - ehsel)
                     + (fmaxf(m1, mp1[jj]) - fmaxf(s1, sp1[jj]));

            sp0[jj] = s0; sp1[jj] = s1; mp0[jj] = m0; mp1[jj] = m1;
        }
    }

    // ---- bottom boundary (vertex row 64): s-row is all zeros ----
    if (warp == NWARP - 1) {
#pragma unroll
        for (int jj = 0; jj < SPG; jj++) {
            float ehsel = (lane == 0) ? 0.0f : sp0[jj];
            acc[jj] += (mp0[jj] - ehsel) + (mp1[jj] - sp1[jj]);
        }
    }

    // ---- warp reduce + atomic ----
#pragma unroll
    for (int jj = 0; jj < SPG; jj++) {
        float v = acc[jj];
#pragma unroll
        for (int o = 16; o > 0; o >>= 1)
            v += __shfl_xor_sync(0xffffffffu, v, o);
        if (lane == 0)
            atomicAdd(&out[img * STEPS + group * SPG + jj], v);
    }
}

extern "C" void kernel_launch(void* const* d_in, const int* in_sizes, int n_in,
                              void* d_out, int out_size) {
    const float* x = (const float*)d_in[0];
    float* out = (float*)d_out;

    int prep_n = NIMG * EIMG;
    prep_kernel<<<(prep_n + 255) / 256, 256>>>(x, out, out_size);
    sig_cubical_ecc_kernel<<<NIMG * GROUPS, THREADS>>>(out);
}

// round 6
// speedup vs baseline: 1.2487x; 1.1269x over previous
#include <cuda_runtime.h>
#include <cstdint>

// SigCubicalEcc round 6.
// Per-pixel sigmoid max-decomposition, E computed in registers per warp
// (no smem, no prep kernel, no syncthreads). 2 RCP + 1 SHFL per warp-row-step.
//
// ECC_j = Sum_v max(m, m_up) - Sum_eh max(s, s_up) - Sum_ev m + Sum_f s
// s = sigma(lam*(t_j - x)) per pixel, m = horizontal pair max; zero padding.
// sigma(lam(t-x)) = rcp(1 + ex2(K*x) * 2^{-K*t}),  K = LAM*log2(e).
// Overflow exact: ex2->inf, fma->inf, rcp.approx(inf)=0.

#define HH 64
#define WW 64
#define STEPS 32
#define GROUPS 16
#define SPG (STEPS / GROUPS)    // 2 steps per block
#define THREADS 128
#define NWARP 4
#define ROWS_PER_WARP 16
#define NIMG 192

__device__ __forceinline__ float ex2_approx(float x) {
    float y;
    asm("ex2.approx.ftz.f32 %0, %1;" : "=f"(y) : "f"(x));
    return y;
}
__device__ __forceinline__ float rcp_approx(float x) {
    float y;
    asm("rcp.approx.ftz.f32 %0, %1;" : "=f"(y) : "f"(x));
    return y;
}

__global__ void zero_out_kernel(float* out, int n) {
    int i = blockIdx.x * blockDim.x + threadIdx.x;
    if (i < n) out[i] = 0.0f;
}

__global__ __launch_bounds__(THREADS)
void sig_cubical_ecc_kernel(const float* __restrict__ x, float* __restrict__ out) {
    const int img   = blockIdx.x >> 4;           // / GROUPS
    const int group = blockIdx.x & (GROUPS - 1);
    const int tid   = threadIdx.x;
    const int lane  = tid & 31;
    const int warp  = tid >> 5;

    const float K = 200.0f * 1.4426950408889634f;   // LAM * log2(e)

    // c_j = 2^(-K * t_j) for this block's steps
    float cj[SPG];
#pragma unroll
    for (int jj = 0; jj < SPG; jj++) {
        int j = group * SPG + jj;
        float tj = 0.02f + (float)j * (0.26f / 31.0f);
        cj[jj] = ex2_approx(-K * tj);
    }

    const float* xi = x + (size_t)img * (HH * WW) + 2 * lane;
    const int r0 = warp * ROWS_PER_WARP;

    float sp0[SPG], sp1[SPG], mp0[SPG], mp1[SPG], acc[SPG];
#pragma unroll
    for (int jj = 0; jj < SPG; jj++) {
        sp0[jj] = 0.0f; sp1[jj] = 0.0f;
        mp0[jj] = 0.0f; mp1[jj] = 0.0f;
        acc[jj] = 0.0f;
    }

    // ---- halo row r0-1 (warp 0: row -1 is padding => all zeros) ----
    if (warp > 0) {
        float2 xv = *reinterpret_cast<const float2*>(xi + (r0 - 1) * WW);
        float ex = ex2_approx(xv.x * K);
        float ey = ex2_approx(xv.y * K);
#pragma unroll
        for (int jj = 0; jj < SPG; jj++) {
            float s0 = rcp_approx(fmaf(ex, cj[jj], 1.0f));
            float s1 = rcp_approx(fmaf(ey, cj[jj], 1.0f));
            float sn = __shfl_down_sync(0xffffffffu, s0, 1);
            sn = (lane == 31) ? 0.0f : sn;
            sp0[jj] = s0; sp1[jj] = s1;
            mp0[jj] = fmaxf(s0, s1);
            mp1[jj] = fmaxf(s1, sn);
        }
    }

    // ---- 16 data rows ----
#pragma unroll 4
    for (int i = 0; i < ROWS_PER_WARP; i++) {
        float2 xv = *reinterpret_cast<const float2*>(xi + (r0 + i) * WW);
        float ex = ex2_approx(xv.x * K);
        float ey = ex2_approx(xv.y * K);
#pragma unroll
        for (int jj = 0; jj < SPG; jj++) {
            float s0 = rcp_approx(fmaf(ex, cj[jj], 1.0f));
            float s1 = rcp_approx(fmaf(ey, cj[jj], 1.0f));
            float sn = __shfl_down_sync(0xffffffffu, s0, 1);
            sn = (lane == 31) ? 0.0f : sn;
            float m0 = fmaxf(s0, s1);
            float m1 = fmaxf(s1, sn);

            float eh    = fmaxf(s0, sp0[jj]);
            float ehsel = (lane == 0) ? s0 : eh;   // left-boundary cancellation
            acc[jj] += (fminf(s0, s1) - m1)
                     + (fmaxf(m0, mp0[jj]) - ehsel)
                     + (fmaxf(m1, mp1[jj]) - fmaxf(s1, sp1[jj]));

            sp0[jj] = s0; sp1[jj] = s1; mp0[jj] = m0; mp1[jj] = m1;
        }
    }

    // ---- bottom boundary (vertex row 64): the row below is all zeros ----
    if (warp == NWARP - 1) {
#pragma unroll
        for (int jj = 0; jj < SPG; jj++) {
            float ehsel = (lane == 0) ? 0.0f : sp0[jj];
            acc[jj] += (mp0[jj] - ehsel) + (mp1[jj] - sp1[jj]);
        }
    }

    // ---- warp reduce + atomic ----
#pragma unroll
    for (int jj = 0; jj < SPG; jj++) {
        float v = acc[jj];
#pragma unroll
        for (int o = 16; o > 0; o >>= 1)
            v += __shfl_xor_sync(0xffffffffu, v, o);
        if (lane == 0)
            atomicAdd(&out[img * STEPS + group * SPG + jj], v);
    }
}

extern "C" void kernel_launch(void* const* d_in, const int* in_sizes, int n_in,
                              void* d_out, int out_size) {
    const float* x = (const float*)d_in[0];
    float* out = (float*)d_out;

    zero_out_kernel<<<(out_size + 255) / 256, 256>>>(out, out_size);
    sig_cubical_ecc_kernel<<<NIMG * GROUPS, THREADS>>>(x, out);
}

// round 7
// speedup vs baseline: 1.3607x; 1.0897x over previous
#include <cuda_runtime.h>
#include <cstdint>

// SigCubicalEcc round 7.
// Per-pixel sigmoid max-decomposition (2 RCP + 1 SHFL per warp-row-step).
// One block per (image, step-group): 8 warps x 8 rows, smem reduction,
// plain store (no atomics, no zero kernel -> single launch).
//
// ECC_j = Sum_v max(m, m_up) - Sum_eh max(s, s_up) - Sum_ev m + Sum_f s
// s = sigma(lam*(t_j - x)) per pixel, m = horizontal pair max; zero padding.
// sigma(lam(t-x)) = rcp(1 + ex2(K*x) * 2^{-K*t}),  K = LAM*log2(e).
// Overflow exact: ex2->inf, fma->inf, rcp.approx(inf)=0.

#define HH 64
#define WW 64
#define STEPS 32
#define GROUPS 16
#define SPG (STEPS / GROUPS)    // 2 steps per block
#define THREADS 256
#define NWARP 8
#define ROWS_PER_WARP 8
#define NIMG 192

__device__ __forceinline__ float ex2_approx(float x) {
    float y;
    asm("ex2.approx.ftz.f32 %0, %1;" : "=f"(y) : "f"(x));
    return y;
}
__device__ __forceinline__ float rcp_approx(float x) {
    float y;
    asm("rcp.approx.ftz.f32 %0, %1;" : "=f"(y) : "f"(x));
    return y;
}

__global__ __launch_bounds__(THREADS)
void sig_cubical_ecc_kernel(const float* __restrict__ x, float* __restrict__ out) {
    __shared__ float red[NWARP][SPG];

    const int img   = blockIdx.x >> 4;           // / GROUPS
    const int group = blockIdx.x & (GROUPS - 1);
    const int tid   = threadIdx.x;
    const int lane  = tid & 31;
    const int warp  = tid >> 5;

    const float K = 200.0f * 1.4426950408889634f;   // LAM * log2(e)

    // c_j = 2^(-K * t_j) for this block's steps
    float cj[SPG];
#pragma unroll
    for (int jj = 0; jj < SPG; jj++) {
        int j = group * SPG + jj;
        float tj = 0.02f + (float)j * (0.26f / 31.0f);
        cj[jj] = ex2_approx(-K * tj);
    }

    const float* xi = x + (size_t)img * (HH * WW) + 2 * lane;
    const int r0 = warp * ROWS_PER_WARP;

    float sp0[SPG], sp1[SPG], mp0[SPG], mp1[SPG], acc[SPG];
#pragma unroll
    for (int jj = 0; jj < SPG; jj++) {
        sp0[jj] = 0.0f; sp1[jj] = 0.0f;
        mp0[jj] = 0.0f; mp1[jj] = 0.0f;
        acc[jj] = 0.0f;
    }

    // ---- halo row r0-1 (warp 0: row -1 is padding => all zeros) ----
    if (warp > 0) {
        float2 xv = *reinterpret_cast<const float2*>(xi + (r0 - 1) * WW);
        float ex = ex2_approx(xv.x * K);
        float ey = ex2_approx(xv.y * K);
#pragma unroll
        for (int jj = 0; jj < SPG; jj++) {
            float s0 = rcp_approx(fmaf(ex, cj[jj], 1.0f));
            float s1 = rcp_approx(fmaf(ey, cj[jj], 1.0f));
            float sn = __shfl_down_sync(0xffffffffu, s0, 1);
            sn = (lane == 31) ? 0.0f : sn;
            sp0[jj] = s0; sp1[jj] = s1;
            mp0[jj] = fmaxf(s0, s1);
            mp1[jj] = fmaxf(s1, sn);
        }
    }

    // ---- 8 data rows ----
#pragma unroll
    for (int i = 0; i < ROWS_PER_WARP; i++) {
        float2 xv = *reinterpret_cast<const float2*>(xi + (r0 + i) * WW);
        float ex = ex2_approx(xv.x * K);
        float ey = ex2_approx(xv.y * K);
#pragma unroll
        for (int jj = 0; jj < SPG; jj++) {
            float s0 = rcp_approx(fmaf(ex, cj[jj], 1.0f));
            float s1 = rcp_approx(fmaf(ey, cj[jj], 1.0f));
            float sn = __shfl_down_sync(0xffffffffu, s0, 1);
            sn = (lane == 31) ? 0.0f : sn;
            float m0 = fmaxf(s0, s1);
            float m1 = fmaxf(s1, sn);

            float eh    = fmaxf(s0, sp0[jj]);
            float ehsel = (lane == 0) ? s0 : eh;   // left-boundary cancellation
            acc[jj] += (fminf(s0, s1) - m1)
                     + (fmaxf(m0, mp0[jj]) - ehsel)
                     + (fmaxf(m1, mp1[jj]) - fmaxf(s1, sp1[jj]));

            sp0[jj] = s0; sp1[jj] = s1; mp0[jj] = m0; mp1[jj] = m1;
        }
    }

    // ---- bottom boundary (vertex row 64): the row below is all zeros ----
    if (warp == NWARP - 1) {
#pragma unroll
        for (int jj = 0; jj < SPG; jj++) {
            float ehsel = (lane == 0) ? 0.0f : sp0[jj];
            acc[jj] += (mp0[jj] - ehsel) + (mp1[jj] - sp1[jj]);
        }
    }

    // ---- warp reduce, then block reduce in smem, single store ----
#pragma unroll
    for (int jj = 0; jj < SPG; jj++) {
        float v = acc[jj];
#pragma unroll
        for (int o = 16; o > 0; o >>= 1)
            v += __shfl_xor_sync(0xffffffffu, v, o);
        if (lane == 0) red[warp][jj] = v;
    }
    __syncthreads();

    if (tid < SPG) {
        float s = 0.0f;
#pragma unroll
        for (int w = 0; w < NWARP; w++) s += red[w][tid];
        out[img * STEPS + group * SPG + tid] = s;
    }
}

extern "C" void kernel_launch(void* const* d_in, const int* in_sizes, int n_in,
                              void* d_out, int out_size) {
    const float* x = (const float*)d_in[0];
    float* out = (float*)d_out;

    sig_cubical_ecc_kernel<<<NIMG * GROUPS, THREADS>>>(x, out);
}